// round 7
// baseline (speedup 1.0000x reference)
#include <cuda_runtime.h>
#include <cstdint>

#define NU 100000
#define NI 50000
#define NE 1000000
#define EMB 64
#define DV 16            // float4 chunks per row

#define TILE 1024
#define NBU ((NU + TILE - 1) / TILE)   // 98
#define NBI ((NI + TILE - 1) / TILE)   // 49

// ---------------------------------------------------------------------------
// __device__ scratch (zero-initialized at module load; no allocations)
// ---------------------------------------------------------------------------
__device__ float g_u1[NU * EMB];
__device__ float g_i1[NI * EMB];
__device__ int   g_degU[NU];        // invariant: zero at kernel_launch entry
__device__ int   g_degI[NI];        // (restored by scan_finish each call)
__device__ int   g_offU[NU + 1];
__device__ int   g_offI[NI + 1];
__device__ float g_invU[NU];
__device__ float g_invI[NI];
__device__ int   g_csrU[NE];
__device__ int   g_csrI[NE];
__device__ int   g_rankU[NE];       // edge's rank within its user's list
__device__ int   g_rankI[NE];       // edge's rank within its item's list
__device__ int   g_partU[NBU];
__device__ int   g_partI[NBI];
__device__ int   g_baseU[NBU];
__device__ int   g_baseI[NBI];

// ---------------------------------------------------------------------------
// (0) degrees + per-edge ranks: 4 edges/thread, returning atomics,
//     coalesced int4 rank stores.
// ---------------------------------------------------------------------------
__global__ void degree_kernel(const int4* __restrict__ es4,
                              const int4* __restrict__ ed4) {
    int t = blockIdx.x * blockDim.x + threadIdx.x;
    if (t < NE / 4) {
        int4 s = __ldg(&es4[t]);
        int4 d = __ldg(&ed4[t]);
        int4 ru, ri;
        ru.x = atomicAdd(&g_degU[s.x], 1);
        ru.y = atomicAdd(&g_degU[s.y], 1);
        ru.z = atomicAdd(&g_degU[s.z], 1);
        ru.w = atomicAdd(&g_degU[s.w], 1);
        ri.x = atomicAdd(&g_degI[d.x], 1);
        ri.y = atomicAdd(&g_degI[d.y], 1);
        ri.z = atomicAdd(&g_degI[d.z], 1);
        ri.w = atomicAdd(&g_degI[d.w], 1);
        reinterpret_cast<int4*>(g_rankU)[t] = ru;
        reinterpret_cast<int4*>(g_rankI)[t] = ri;
    }
}

// ---------------------------------------------------------------------------
// (1) per-tile partial sums
// ---------------------------------------------------------------------------
__global__ void __launch_bounds__(256)
scan_partials() {
    __shared__ int ssum[256];
    int b = blockIdx.x;
    bool isU = (b < NBU);
    int tileIdx = isU ? b : b - NBU;
    int n       = isU ? NU : NI;
    const int4* deg4 = reinterpret_cast<const int4*>(isU ? g_degU : g_degI);
    int* part = isU ? g_partU : g_partI;

    int i4 = tileIdx * (TILE / 4) + threadIdx.x;
    int s = 0;
    if (i4 * 4 < n) {
        int4 v = deg4[i4];
        s = v.x + v.y + v.z + v.w;
    }
    ssum[threadIdx.x] = s;
    __syncthreads();
    for (int st = 128; st > 0; st >>= 1) {
        if (threadIdx.x < st) ssum[threadIdx.x] += ssum[threadIdx.x + st];
        __syncthreads();
    }
    if (threadIdx.x == 0) part[tileIdx] = ssum[0];
}

// ---------------------------------------------------------------------------
// (2) scan the 147 tile sums
// ---------------------------------------------------------------------------
__global__ void __launch_bounds__(256)
scan_bases() {
    __shared__ int sp[NBU + NBI];
    int t = threadIdx.x;
    if (t < NBU) sp[t]       = g_partU[t];
    if (t < NBI) sp[NBU + t] = g_partI[t];
    __syncthreads();
    if (t == 0) {
        int acc = 0;
        for (int i = 0; i < NBU; i++) { int v = sp[i]; sp[i] = acc; acc += v; }
        g_offU[NU] = acc;
        acc = 0;
        for (int i = 0; i < NBI; i++) { int v = sp[NBU + i]; sp[NBU + i] = acc; acc += v; }
        g_offI[NI] = acc;
    }
    __syncthreads();
    if (t < NBU) g_baseU[t] = sp[t];
    if (t < NBI) g_baseI[t] = sp[NBU + t];
}

// ---------------------------------------------------------------------------
// (3) per-tile local scan -> off/inv; also re-zeroes deg (invariant).
// ---------------------------------------------------------------------------
__global__ void __launch_bounds__(256)
scan_finish() {
    __shared__ int ssum[256];
    int b = blockIdx.x;
    bool isU = (b < NBU);
    int tileIdx = isU ? b : b - NBU;
    int n       = isU ? NU : NI;
    int* deg   = isU ? g_degU : g_degI;
    int* off   = isU ? g_offU : g_offI;
    float* inv = isU ? g_invU : g_invI;
    int base   = isU ? g_baseU[tileIdx] : g_baseI[tileIdx];

    int t = threadIdx.x;
    int i4 = tileIdx * (TILE / 4) + t;
    int e0 = i4 * 4;
    int4 v = make_int4(0, 0, 0, 0);
    bool act = (e0 < n);
    if (act) v = reinterpret_cast<const int4*>(deg)[i4];
    int s = v.x + v.y + v.z + v.w;

    ssum[t] = s;
    __syncthreads();
    for (int st = 1; st < 256; st <<= 1) {
        int o = (t >= st) ? ssum[t - st] : 0;
        __syncthreads();
        ssum[t] += o;
        __syncthreads();
    }
    int pfx = base + ssum[t] - s;

    if (act) {
        off[e0 + 0] = pfx;  inv[e0 + 0] = v.x ? 1.0f / v.x : 0.f;  pfx += v.x;
        off[e0 + 1] = pfx;  inv[e0 + 1] = v.y ? 1.0f / v.y : 0.f;  pfx += v.y;
        off[e0 + 2] = pfx;  inv[e0 + 2] = v.z ? 1.0f / v.z : 0.f;  pfx += v.z;
        off[e0 + 3] = pfx;  inv[e0 + 3] = v.w ? 1.0f / v.w : 0.f;
        // restore zero invariant for next call
        reinterpret_cast<int4*>(deg)[i4] = make_int4(0, 0, 0, 0);
    }
}

// ---------------------------------------------------------------------------
// (4) build CSR — atomic-free: slot = off[node] + precomputed rank
// ---------------------------------------------------------------------------
__global__ void build_csr(const int4* __restrict__ es4,
                          const int4* __restrict__ ed4) {
    int t = blockIdx.x * blockDim.x + threadIdx.x;
    if (t < NE / 4) {
        int4 s  = __ldg(&es4[t]);
        int4 d  = __ldg(&ed4[t]);
        int4 ru = reinterpret_cast<const int4*>(g_rankU)[t];
        int4 ri = reinterpret_cast<const int4*>(g_rankI)[t];
        g_csrI[__ldg(&g_offI[d.x]) + ri.x] = s.x;
        g_csrI[__ldg(&g_offI[d.y]) + ri.y] = s.y;
        g_csrI[__ldg(&g_offI[d.z]) + ri.z] = s.z;
        g_csrI[__ldg(&g_offI[d.w]) + ri.w] = s.w;
        g_csrU[__ldg(&g_offU[s.x]) + ru.x] = d.x;
        g_csrU[__ldg(&g_offU[s.y]) + ru.y] = d.y;
        g_csrU[__ldg(&g_offU[s.z]) + ru.z] = d.z;
        g_csrU[__ldg(&g_offU[s.w]) + ru.w] = d.w;
    }
}

// ---------------------------------------------------------------------------
// (5)/(6) fused round: one WARP per row, 2 neighbor streams.
//   Predicated 4-wide batches: always 4 gathers in flight per half,
//   clamped indices + 0/1 FMA weights for the tail (keeps MLP=4 even for
//   short user rows).
// ---------------------------------------------------------------------------
__global__ void __launch_bounds__(256)
round_kernel(const float4* __restrict__ uin,
             const float4* __restrict__ iin,
             const float*  __restrict__ usw,
             const float*  __restrict__ isw,
             float4* __restrict__ uout,
             float4* __restrict__ iout) {
    int warpId = (blockIdx.x * blockDim.x + threadIdx.x) >> 5;
    int lane   = threadIdx.x & 31;
    int c      = lane & 15;
    int h      = lane >> 4;
    if (warpId >= NI + NU) return;

    const float4* src;
    const int*    adj;
    int off, end, outIdx;
    float inv, sw;
    float4 x;
    float4* outp;

    if (warpId < NI) {
        int r = warpId;
        off = g_offI[r]; end = g_offI[r + 1];
        src = uin; adj = g_csrI;
        inv = g_invI[r]; sw = isw[r];
        outIdx = r * DV + c;
        x = iin[outIdx];
        outp = iout;
    } else {
        int r = warpId - NI;
        off = g_offU[r]; end = g_offU[r + 1];
        src = iin; adj = g_csrU;
        inv = g_invU[r]; sw = usw[r];
        outIdx = r * DV + c;
        x = uin[outIdx];
        outp = uout;
    }

    float4 acc = make_float4(0.f, 0.f, 0.f, 0.f);
    for (int k = off + h; k < end; k += 8) {
        int last = end - 1;
        int k1 = min(k + 2, last);
        int k2 = min(k + 4, last);
        int k3 = min(k + 6, last);
        float w1 = (k + 2 < end) ? 1.0f : 0.0f;
        float w2 = (k + 4 < end) ? 1.0f : 0.0f;
        float w3 = (k + 6 < end) ? 1.0f : 0.0f;
        int s0 = __ldg(&adj[k ]);
        int s1 = __ldg(&adj[k1]);
        int s2 = __ldg(&adj[k2]);
        int s3 = __ldg(&adj[k3]);
        float4 a = src[s0 * DV + c];
        float4 b = src[s1 * DV + c];
        float4 d = src[s2 * DV + c];
        float4 e = src[s3 * DV + c];
        acc.x += a.x + b.x * w1 + d.x * w2 + e.x * w3;
        acc.y += a.y + b.y * w1 + d.y * w2 + e.y * w3;
        acc.z += a.z + b.z * w1 + d.z * w2 + e.z * w3;
        acc.w += a.w + b.w * w1 + d.w * w2 + e.w * w3;
    }

    acc.x += __shfl_xor_sync(0xffffffffu, acc.x, 16);
    acc.y += __shfl_xor_sync(0xffffffffu, acc.y, 16);
    acc.z += __shfl_xor_sync(0xffffffffu, acc.z, 16);
    acc.w += __shfl_xor_sync(0xffffffffu, acc.w, 16);

    if (h == 0) {
        float4 r;
        r.x = acc.x * inv + x.x * sw;
        r.y = acc.y * inv + x.y * sw;
        r.z = acc.z * inv + x.z * sw;
        r.w = acc.w * inv + x.w * sw;
        outp[outIdx] = r;
    }
}

// ---------------------------------------------------------------------------
// Launch
// ---------------------------------------------------------------------------
extern "C" void kernel_launch(void* const* d_in, const int* in_sizes, int n_in,
                              void* d_out, int out_size) {
    const float* user_emb = (const float*)d_in[0];
    const float* item_emb = (const float*)d_in[1];
    const float* u_sw     = (const float*)d_in[2];
    const float* i_sw     = (const float*)d_in[3];
    const int*   e_src    = (const int*)d_in[4];
    const int*   e_dst    = (const int*)d_in[5];

    float* out_u = (float*)d_out;
    float* out_i = (float*)d_out + (int64_t)NU * EMB;

    void* p;
    cudaGetSymbolAddress(&p, g_u1); float4* u1p = (float4*)p;
    cudaGetSymbolAddress(&p, g_i1); float4* i1p = (float4*)p;

    const int TPB = 256;
    const int eThreads = NE / 4;

    degree_kernel<<<(eThreads + TPB - 1) / TPB, TPB>>>(
        (const int4*)e_src, (const int4*)e_dst);

    scan_partials<<<NBU + NBI, 256>>>();
    scan_bases<<<1, 256>>>();
    scan_finish<<<NBU + NBI, 256>>>();

    build_csr<<<(eThreads + TPB - 1) / TPB, TPB>>>(
        (const int4*)e_src, (const int4*)e_dst);

    int rows = NI + NU;
    int rblocks = (rows * 32 + TPB - 1) / TPB;

    round_kernel<<<rblocks, TPB>>>((const float4*)user_emb,
                                   (const float4*)item_emb,
                                   u_sw, i_sw, u1p, i1p);

    round_kernel<<<rblocks, TPB>>>((const float4*)u1p,
                                   (const float4*)i1p,
                                   u_sw, i_sw,
                                   (float4*)out_u, (float4*)out_i);
}

// round 8
// speedup vs baseline: 1.3001x; 1.3001x over previous
#include <cuda_runtime.h>
#include <cstdint>

#define NU 100000
#define NI 50000
#define NE 1000000
#define EMB 64
#define DV 16            // float4 chunks per row

#define TILE 1024
#define NBU ((NU + TILE - 1) / TILE)   // 98
#define NBI ((NI + TILE - 1) / TILE)   // 49

// ---------------------------------------------------------------------------
// __device__ scratch (zero-initialized at module load; no allocations)
// ---------------------------------------------------------------------------
__device__ float g_u1[NU * EMB];
__device__ float g_i1[NI * EMB];
__device__ int   g_degU[NU];        // invariant: zero at kernel_launch entry
__device__ int   g_degI[NI];        // (restored by scan_finish each call)
__device__ int   g_offU[NU + 1];
__device__ int   g_offI[NI + 1];
__device__ float g_invU[NU];
__device__ float g_invI[NI];
__device__ int   g_csrU[NE];
__device__ int   g_csrI[NE];
__device__ int   g_rankU[NE];
__device__ int   g_rankI[NE];
__device__ int   g_partU[NBU];
__device__ int   g_partI[NBI];
__device__ int   g_baseU[NBU];
__device__ int   g_baseI[NBI];

// ---------------------------------------------------------------------------
// (0) degrees + per-edge ranks (returning atomics, coalesced rank stores)
// ---------------------------------------------------------------------------
__global__ void degree_kernel(const int4* __restrict__ es4,
                              const int4* __restrict__ ed4) {
    int t = blockIdx.x * blockDim.x + threadIdx.x;
    if (t < NE / 4) {
        int4 s = __ldg(&es4[t]);
        int4 d = __ldg(&ed4[t]);
        int4 ru, ri;
        ru.x = atomicAdd(&g_degU[s.x], 1);
        ru.y = atomicAdd(&g_degU[s.y], 1);
        ru.z = atomicAdd(&g_degU[s.z], 1);
        ru.w = atomicAdd(&g_degU[s.w], 1);
        ri.x = atomicAdd(&g_degI[d.x], 1);
        ri.y = atomicAdd(&g_degI[d.y], 1);
        ri.z = atomicAdd(&g_degI[d.z], 1);
        ri.w = atomicAdd(&g_degI[d.w], 1);
        reinterpret_cast<int4*>(g_rankU)[t] = ru;
        reinterpret_cast<int4*>(g_rankI)[t] = ri;
    }
}

// ---------------------------------------------------------------------------
// (1) per-tile partial sums
// ---------------------------------------------------------------------------
__global__ void __launch_bounds__(256)
scan_partials() {
    __shared__ int ssum[256];
    int b = blockIdx.x;
    bool isU = (b < NBU);
    int tileIdx = isU ? b : b - NBU;
    int n       = isU ? NU : NI;
    const int4* deg4 = reinterpret_cast<const int4*>(isU ? g_degU : g_degI);
    int* part = isU ? g_partU : g_partI;

    int i4 = tileIdx * (TILE / 4) + threadIdx.x;
    int s = 0;
    if (i4 * 4 < n) {
        int4 v = deg4[i4];
        s = v.x + v.y + v.z + v.w;
    }
    ssum[threadIdx.x] = s;
    __syncthreads();
    for (int st = 128; st > 0; st >>= 1) {
        if (threadIdx.x < st) ssum[threadIdx.x] += ssum[threadIdx.x + st];
        __syncthreads();
    }
    if (threadIdx.x == 0) part[tileIdx] = ssum[0];
}

// ---------------------------------------------------------------------------
// (2) scan the 147 tile sums
// ---------------------------------------------------------------------------
__global__ void __launch_bounds__(256)
scan_bases() {
    __shared__ int sp[NBU + NBI];
    int t = threadIdx.x;
    if (t < NBU) sp[t]       = g_partU[t];
    if (t < NBI) sp[NBU + t] = g_partI[t];
    __syncthreads();
    if (t == 0) {
        int acc = 0;
        for (int i = 0; i < NBU; i++) { int v = sp[i]; sp[i] = acc; acc += v; }
        g_offU[NU] = acc;
        acc = 0;
        for (int i = 0; i < NBI; i++) { int v = sp[NBU + i]; sp[NBU + i] = acc; acc += v; }
        g_offI[NI] = acc;
    }
    __syncthreads();
    if (t < NBU) g_baseU[t] = sp[t];
    if (t < NBI) g_baseI[t] = sp[NBU + t];
}

// ---------------------------------------------------------------------------
// (3) per-tile local scan -> off/inv; re-zeroes deg (invariant).
// ---------------------------------------------------------------------------
__global__ void __launch_bounds__(256)
scan_finish() {
    __shared__ int ssum[256];
    int b = blockIdx.x;
    bool isU = (b < NBU);
    int tileIdx = isU ? b : b - NBU;
    int n       = isU ? NU : NI;
    int* deg   = isU ? g_degU : g_degI;
    int* off   = isU ? g_offU : g_offI;
    float* inv = isU ? g_invU : g_invI;
    int base   = isU ? g_baseU[tileIdx] : g_baseI[tileIdx];

    int t = threadIdx.x;
    int i4 = tileIdx * (TILE / 4) + t;
    int e0 = i4 * 4;
    int4 v = make_int4(0, 0, 0, 0);
    bool act = (e0 < n);
    if (act) v = reinterpret_cast<const int4*>(deg)[i4];
    int s = v.x + v.y + v.z + v.w;

    ssum[t] = s;
    __syncthreads();
    for (int st = 1; st < 256; st <<= 1) {
        int o = (t >= st) ? ssum[t - st] : 0;
        __syncthreads();
        ssum[t] += o;
        __syncthreads();
    }
    int pfx = base + ssum[t] - s;

    if (act) {
        off[e0 + 0] = pfx;  inv[e0 + 0] = v.x ? 1.0f / v.x : 0.f;  pfx += v.x;
        off[e0 + 1] = pfx;  inv[e0 + 1] = v.y ? 1.0f / v.y : 0.f;  pfx += v.y;
        off[e0 + 2] = pfx;  inv[e0 + 2] = v.z ? 1.0f / v.z : 0.f;  pfx += v.z;
        off[e0 + 3] = pfx;  inv[e0 + 3] = v.w ? 1.0f / v.w : 0.f;
        reinterpret_cast<int4*>(deg)[i4] = make_int4(0, 0, 0, 0);
    }
}

// ---------------------------------------------------------------------------
// (4) build CSR — atomic-free: slot = off[node] + precomputed rank
// ---------------------------------------------------------------------------
__global__ void build_csr(const int4* __restrict__ es4,
                          const int4* __restrict__ ed4) {
    int t = blockIdx.x * blockDim.x + threadIdx.x;
    if (t < NE / 4) {
        int4 s  = __ldg(&es4[t]);
        int4 d  = __ldg(&ed4[t]);
        int4 ru = reinterpret_cast<const int4*>(g_rankU)[t];
        int4 ri = reinterpret_cast<const int4*>(g_rankI)[t];
        g_csrI[__ldg(&g_offI[d.x]) + ri.x] = s.x;
        g_csrI[__ldg(&g_offI[d.y]) + ri.y] = s.y;
        g_csrI[__ldg(&g_offI[d.z]) + ri.z] = s.z;
        g_csrI[__ldg(&g_offI[d.w]) + ri.w] = s.w;
        g_csrU[__ldg(&g_offU[s.x]) + ru.x] = d.x;
        g_csrU[__ldg(&g_offU[s.y]) + ru.y] = d.y;
        g_csrU[__ldg(&g_offU[s.z]) + ru.z] = d.z;
        g_csrU[__ldg(&g_offU[s.w]) + ru.w] = d.w;
    }
}

// ---------------------------------------------------------------------------
// (5)/(6) fused round: one WARP per row, 2 neighbor streams (as R6),
//   with predicate-GUARDED extra loads: guarded-off LDG issues no traffic,
//   MLP stays 4 on short rows, zero duplicate gathers.
// ---------------------------------------------------------------------------
__global__ void __launch_bounds__(256)
round_kernel(const float4* __restrict__ uin,
             const float4* __restrict__ iin,
             const float*  __restrict__ usw,
             const float*  __restrict__ isw,
             float4* __restrict__ uout,
             float4* __restrict__ iout) {
    int warpId = (blockIdx.x * blockDim.x + threadIdx.x) >> 5;
    int lane   = threadIdx.x & 31;
    int c      = lane & 15;
    int h      = lane >> 4;
    if (warpId >= NI + NU) return;

    const float4* src;
    const int*    adj;
    int off, end, outIdx;
    float inv, sw;
    float4 x;
    float4* outp;

    if (warpId < NI) {
        int r = warpId;
        off = g_offI[r]; end = g_offI[r + 1];
        src = uin; adj = g_csrI;
        inv = g_invI[r]; sw = isw[r];
        outIdx = r * DV + c;
        x = iin[outIdx];
        outp = iout;
    } else {
        int r = warpId - NI;
        off = g_offU[r]; end = g_offU[r + 1];
        src = iin; adj = g_csrU;
        inv = g_invU[r]; sw = usw[r];
        outIdx = r * DV + c;
        x = uin[outIdx];
        outp = uout;
    }

    float4 acc = make_float4(0.f, 0.f, 0.f, 0.f);
    for (int k = off + h; k < end; k += 8) {
        bool p1 = (k + 2 < end);
        bool p2 = (k + 4 < end);
        bool p3 = (k + 6 < end);
        int last = end - 1;
        // index loads clamped (same cache line, negligible cost)
        int s0 = __ldg(&adj[k]);
        int s1 = __ldg(&adj[min(k + 2, last)]);
        int s2 = __ldg(&adj[min(k + 4, last)]);
        int s3 = __ldg(&adj[min(k + 6, last)]);
        // row gathers guarded: no traffic when predicated off
        float4 a = src[s0 * DV + c];
        float4 b = make_float4(0.f, 0.f, 0.f, 0.f);
        float4 d = make_float4(0.f, 0.f, 0.f, 0.f);
        float4 e = make_float4(0.f, 0.f, 0.f, 0.f);
        if (p1) b = src[s1 * DV + c];
        if (p2) d = src[s2 * DV + c];
        if (p3) e = src[s3 * DV + c];
        acc.x += (a.x + b.x) + (d.x + e.x);
        acc.y += (a.y + b.y) + (d.y + e.y);
        acc.z += (a.z + b.z) + (d.z + e.z);
        acc.w += (a.w + b.w) + (d.w + e.w);
    }

    acc.x += __shfl_xor_sync(0xffffffffu, acc.x, 16);
    acc.y += __shfl_xor_sync(0xffffffffu, acc.y, 16);
    acc.z += __shfl_xor_sync(0xffffffffu, acc.z, 16);
    acc.w += __shfl_xor_sync(0xffffffffu, acc.w, 16);

    if (h == 0) {
        float4 r;
        r.x = acc.x * inv + x.x * sw;
        r.y = acc.y * inv + x.y * sw;
        r.z = acc.z * inv + x.z * sw;
        r.w = acc.w * inv + x.w * sw;
        outp[outIdx] = r;
    }
}

// ---------------------------------------------------------------------------
// Launch
// ---------------------------------------------------------------------------
extern "C" void kernel_launch(void* const* d_in, const int* in_sizes, int n_in,
                              void* d_out, int out_size) {
    const float* user_emb = (const float*)d_in[0];
    const float* item_emb = (const float*)d_in[1];
    const float* u_sw     = (const float*)d_in[2];
    const float* i_sw     = (const float*)d_in[3];
    const int*   e_src    = (const int*)d_in[4];
    const int*   e_dst    = (const int*)d_in[5];

    float* out_u = (float*)d_out;
    float* out_i = (float*)d_out + (int64_t)NU * EMB;

    void* p;
    cudaGetSymbolAddress(&p, g_u1); float4* u1p = (float4*)p;
    cudaGetSymbolAddress(&p, g_i1); float4* i1p = (float4*)p;

    const int TPB = 256;
    const int eThreads = NE / 4;

    degree_kernel<<<(eThreads + TPB - 1) / TPB, TPB>>>(
        (const int4*)e_src, (const int4*)e_dst);

    scan_partials<<<NBU + NBI, 256>>>();
    scan_bases<<<1, 256>>>();
    scan_finish<<<NBU + NBI, 256>>>();

    build_csr<<<(eThreads + TPB - 1) / TPB, TPB>>>(
        (const int4*)e_src, (const int4*)e_dst);

    int rows = NI + NU;
    int rblocks = (rows * 32 + TPB - 1) / TPB;

    round_kernel<<<rblocks, TPB>>>((const float4*)user_emb,
                                   (const float4*)item_emb,
                                   u_sw, i_sw, u1p, i1p);

    round_kernel<<<rblocks, TPB>>>((const float4*)u1p,
                                   (const float4*)i1p,
                                   u_sw, i_sw,
                                   (float4*)out_u, (float4*)out_i);
}